// round 2
// baseline (speedup 1.0000x reference)
#include <cuda_runtime.h>
#include <cuda_bf16.h>
#include <cstdint>

#define N_NODES 100000
#define N_EDGES 400000
#define HID 128
#define HEADS 4
#define N_GRAPHS 2000
#define NEG_SLOPE 0.2f
#define BN_EPS 1e-5f
#define N_ITEMS (N_EDGES + N_NODES)   // edges + self loops

// ---------------- scratch (static device globals; no runtime alloc) ----------
__device__ float g_dinv[N_NODES];                 // deg -> rsqrt(deg)
__device__ float g_h[(size_t)N_NODES * HID];      // current node features
__device__ float g_t[(size_t)N_NODES * HID];      // GEMM output t = h @ W
__device__ float g_agg[(size_t)N_NODES * HID];    // scatter accumulator
__device__ float g_hh[(size_t)N_NODES * HEADS * HID]; // GAT transformed feats
__device__ float g_as[(size_t)N_NODES * HEADS];
__device__ float g_ad[(size_t)N_NODES * HEADS];
__device__ unsigned g_emax[(size_t)N_NODES * HEADS];  // monotonic-uint max, then float bits
__device__ float g_denom[(size_t)N_NODES * HEADS];
__device__ float g_gsum[(size_t)N_GRAPHS * HID];
__device__ float g_cnt[N_GRAPHS];

// ---------------- small helpers ----------------------------------------------
__global__ void zero_kernel(float* p, size_t n) {
    size_t i = (size_t)blockIdx.x * blockDim.x + threadIdx.x;
    size_t stride = (size_t)gridDim.x * blockDim.x;
    for (; i < n; i += stride) p[i] = 0.f;
}

__global__ void deg_init_kernel() {
    int i = blockIdx.x * blockDim.x + threadIdx.x;
    if (i < N_NODES) g_dinv[i] = 1.0f;   // self loop
}
__global__ void deg_accum_kernel(const int* __restrict__ dst) {
    int e = blockIdx.x * blockDim.x + threadIdx.x;
    if (e < N_EDGES) atomicAdd(&g_dinv[dst[e]], 1.0f);
}
__global__ void deg_finish_kernel() {
    int i = blockIdx.x * blockDim.x + threadIdx.x;
    if (i < N_NODES) g_dinv[i] = rsqrtf(g_dinv[i]);
}

// ---------------- SGEMM:  Out[N,C] = A[N,128] @ W[128,C] ---------------------
// 64-row x 128-col tile per CTA, 256 threads, 8x4 register microtile.
template <int C>
__global__ void gemm_k128(const float* __restrict__ A, const float* __restrict__ W,
                          float* __restrict__ Out) {
    __shared__ float As[64][32];
    __shared__ float Bs[32][128];
    const int tid = threadIdx.x;
    const int row0 = blockIdx.x * 64;
    const int cb = blockIdx.y * 128;
    const int ty = tid >> 5;            // warp id 0..7 -> row group
    const int c0 = (tid & 31) * 4;      // col within 128-tile
    float acc[8][4];
#pragma unroll
    for (int i = 0; i < 8; i++)
#pragma unroll
        for (int j = 0; j < 4; j++) acc[i][j] = 0.f;

    for (int kt = 0; kt < 128; kt += 32) {
        // load A tile (64x32) : 512 float4 slots
#pragma unroll
        for (int i = 0; i < 2; i++) {
            int s = tid + i * 256;
            int r = s >> 3, k4 = (s & 7) * 4;
            int row = row0 + r;
            float4 v = make_float4(0.f, 0.f, 0.f, 0.f);
            if (row < N_NODES) v = *(const float4*)&A[(size_t)row * 128 + kt + k4];
            *(float4*)&As[r][k4] = v;
        }
        // load B tile (32x128) : 1024 float4 slots
#pragma unroll
        for (int i = 0; i < 4; i++) {
            int s = tid + i * 256;
            int k = s >> 5, c4 = (s & 31) * 4;
            *(float4*)&Bs[k][c4] = *(const float4*)&W[(size_t)(kt + k) * C + cb + c4];
        }
        __syncthreads();
#pragma unroll
        for (int k = 0; k < 32; k++) {
            float4 b = *(float4*)&Bs[k][c0];
#pragma unroll
            for (int i = 0; i < 8; i++) {
                float a = As[ty * 8 + i][k];
                acc[i][0] += a * b.x; acc[i][1] += a * b.y;
                acc[i][2] += a * b.z; acc[i][3] += a * b.w;
            }
        }
        __syncthreads();
    }
#pragma unroll
    for (int i = 0; i < 8; i++) {
        int row = row0 + ty * 8 + i;
        if (row < N_NODES) {
            float4 v = make_float4(acc[i][0], acc[i][1], acc[i][2], acc[i][3]);
            *(float4*)&Out[(size_t)row * C + cb + c0] = v;
        }
    }
}

// ---------------- GCN scatter: agg[dst] += t[src] * dinv[s]*dinv[d] ----------
// one warp per (edge or self-loop) item
__global__ void gcn_scatter_kernel(const int* __restrict__ src, const int* __restrict__ dst) {
    int warp = (blockIdx.x * blockDim.x + threadIdx.x) >> 5;
    int lane = threadIdx.x & 31;
    if (warp >= N_ITEMS) return;
    int s, d;
    if (warp < N_EDGES) { s = src[warp]; d = dst[warp]; }
    else { s = d = warp - N_EDGES; }
    float w = g_dinv[s] * g_dinv[d];
    const float* ts = g_t + (size_t)s * HID;
    float* ag = g_agg + (size_t)d * HID;
#pragma unroll
    for (int j = 0; j < 4; j++) {
        int c = lane + 32 * j;
        atomicAdd(&ag[c], ts[c] * w);
    }
}

// ---------------- BN(eval) + ReLU + residual ---------------------------------
__global__ void bn_relu_kernel(const float* __restrict__ b, const float* __restrict__ gamma,
                               const float* __restrict__ beta, const float* __restrict__ mean,
                               const float* __restrict__ var, int residual) {
    size_t idx = (size_t)blockIdx.x * blockDim.x + threadIdx.x;
    if (idx >= (size_t)N_NODES * HID) return;
    int c = (int)(idx & (HID - 1));
    float v = g_agg[idx] + b[c];
    v = (v - mean[c]) * rsqrtf(var[c] + BN_EPS) * gamma[c] + beta[c];
    v = fmaxf(v, 0.f);
    g_h[idx] = residual ? (g_h[idx] + v) : v;
}

// ---------------- GAT: per-node attention dots -------------------------------
// one warp per node: a_s[n,h] = <hh[n,h,:], att_src[h,:]> ; same for a_d
__global__ void att_dots_kernel(const float* __restrict__ att_src,
                                const float* __restrict__ att_dst) {
    int warp = (blockIdx.x * blockDim.x + threadIdx.x) >> 5;
    int lane = threadIdx.x & 31;
    if (warp >= N_NODES) return;
    const float* hh = g_hh + (size_t)warp * HEADS * HID;
#pragma unroll
    for (int h = 0; h < HEADS; h++) {
        float ss = 0.f, sd = 0.f;
#pragma unroll
        for (int j = 0; j < 4; j++) {
            int c = lane + 32 * j;
            float v = hh[h * HID + c];
            ss += v * att_src[h * HID + c];
            sd += v * att_dst[h * HID + c];
        }
#pragma unroll
        for (int o = 16; o; o >>= 1) {
            ss += __shfl_xor_sync(0xffffffffu, ss, o);
            sd += __shfl_xor_sync(0xffffffffu, sd, o);
        }
        if (lane == 0) {
            g_as[warp * HEADS + h] = ss;
            g_ad[warp * HEADS + h] = sd;
        }
    }
}

__device__ __forceinline__ float leaky(float x) { return x > 0.f ? x : NEG_SLOPE * x; }
__device__ __forceinline__ unsigned fmap(float f) {
    unsigned u = __float_as_uint(f);
    return (u & 0x80000000u) ? ~u : (u | 0x80000000u);
}

// segment max over dst via atomicMax on monotonic uint key
__global__ void att_emax_kernel(const int* __restrict__ src, const int* __restrict__ dst) {
    int idx = blockIdx.x * blockDim.x + threadIdx.x;
    if (idx >= N_ITEMS * HEADS) return;
    int item = idx >> 2, h = idx & 3;
    int s, d;
    if (item < N_EDGES) { s = src[item]; d = dst[item]; }
    else { s = d = item - N_EDGES; }
    float e = leaky(g_as[s * HEADS + h] + g_ad[d * HEADS + h]);
    atomicMax(&g_emax[d * HEADS + h], fmap(e));
}

__global__ void att_emax_decode_kernel() {
    int idx = blockIdx.x * blockDim.x + threadIdx.x;
    if (idx >= N_NODES * HEADS) return;
    unsigned m = g_emax[idx];
    unsigned u = (m & 0x80000000u) ? (m ^ 0x80000000u) : ~m;
    g_emax[idx] = u;   // now holds float bits
}

__global__ void att_denom_kernel(const int* __restrict__ src, const int* __restrict__ dst) {
    int idx = blockIdx.x * blockDim.x + threadIdx.x;
    if (idx >= N_ITEMS * HEADS) return;
    int item = idx >> 2, h = idx & 3;
    int s, d;
    if (item < N_EDGES) { s = src[item]; d = dst[item]; }
    else { s = d = item - N_EDGES; }
    float e = leaky(g_as[s * HEADS + h] + g_ad[d * HEADS + h]);
    float mx = __uint_as_float(g_emax[d * HEADS + h]);
    atomicAdd(&g_denom[d * HEADS + h], expf(e - mx));
}

// weighted aggregation with head-mean folded in: agg[d,c] += 0.25*sum_h alpha*hh[s,h,c]
__global__ void att_agg_kernel(const int* __restrict__ src, const int* __restrict__ dst) {
    int warp = (blockIdx.x * blockDim.x + threadIdx.x) >> 5;
    int lane = threadIdx.x & 31;
    if (warp >= N_ITEMS) return;
    int s, d;
    if (warp < N_EDGES) { s = src[warp]; d = dst[warp]; }
    else { s = d = warp - N_EDGES; }
    float alpha[HEADS];
#pragma unroll
    for (int h = 0; h < HEADS; h++) {
        float e = leaky(g_as[s * HEADS + h] + g_ad[d * HEADS + h]);
        float mx = __uint_as_float(g_emax[d * HEADS + h]);
        float ex = expf(e - mx);
        alpha[h] = 0.25f * ex / (g_denom[d * HEADS + h] + 1e-16f);
    }
    const float* hh = g_hh + (size_t)s * HEADS * HID;
    float* ag = g_agg + (size_t)d * HID;
#pragma unroll
    for (int j = 0; j < 4; j++) {
        int c = lane + 32 * j;
        float v = alpha[0] * hh[c] + alpha[1] * hh[HID + c] +
                  alpha[2] * hh[2 * HID + c] + alpha[3] * hh[3 * HID + c];
        atomicAdd(&ag[c], v);
    }
}

__global__ void add_gat_kernel(const float* __restrict__ gat_b) {
    size_t idx = (size_t)blockIdx.x * blockDim.x + threadIdx.x;
    if (idx >= (size_t)N_NODES * HID) return;
    int c = (int)(idx & (HID - 1));
    g_h[idx] += g_agg[idx] + gat_b[c];
}

// ---------------- graph mean pool --------------------------------------------
__global__ void pool_kernel(const int* __restrict__ batch) {
    int warp = (blockIdx.x * blockDim.x + threadIdx.x) >> 5;
    int lane = threadIdx.x & 31;
    if (warp >= N_NODES) return;
    int b = batch[warp];
    const float* hn = g_h + (size_t)warp * HID;
    float* gs = g_gsum + (size_t)b * HID;
#pragma unroll
    for (int j = 0; j < 4; j++) {
        int c = lane + 32 * j;
        atomicAdd(&gs[c], hn[c]);
    }
    if (lane == 0) atomicAdd(&g_cnt[b], 1.0f);
}

// ---------------- classifier MLP: 128 -> 64 -> 32 -> 1 -----------------------
__global__ void mlp_kernel(const float* __restrict__ c1W, const float* __restrict__ c1b,
                           const float* __restrict__ c2W, const float* __restrict__ c2b,
                           const float* __restrict__ c3W, const float* __restrict__ c3b,
                           float* __restrict__ out) {
    int g = blockIdx.x;
    int tid = threadIdx.x;   // 64 threads
    __shared__ float gv[128];
    __shared__ float z1[64];
    __shared__ float z2[32];
    float cnt = fmaxf(g_cnt[g], 1.0f);
    for (int c = tid; c < 128; c += 64) gv[c] = g_gsum[(size_t)g * HID + c] / cnt;
    __syncthreads();
    {
        float s = c1b[tid];
#pragma unroll 8
        for (int k = 0; k < 128; k++) s += gv[k] * c1W[k * 64 + tid];
        z1[tid] = fmaxf(s, 0.f);
    }
    __syncthreads();
    if (tid < 32) {
        float s = c2b[tid];
#pragma unroll 8
        for (int k = 0; k < 64; k++) s += z1[k] * c2W[k * 32 + tid];
        z2[tid] = fmaxf(s, 0.f);
        __syncwarp();
        float p = z2[tid] * c3W[tid];
#pragma unroll
        for (int o = 16; o; o >>= 1) p += __shfl_xor_sync(0xffffffffu, p, o);
        if (tid == 0) out[g] = p + c3b[0];
    }
}

// -----------------------------------------------------------------------------
static inline int cdiv(long long a, int b) { return (int)((a + b - 1) / b); }

extern "C" void kernel_launch(void* const* d_in, const int* in_sizes, int n_in,
                              void* d_out, int out_size) {
    const float* x      = (const float*)d_in[0];
    const int*   ei     = (const int*)d_in[1];
    const int*   batch  = (const int*)d_in[2];
    const float* gcn_W  = (const float*)d_in[3];
    const float* gcn_b  = (const float*)d_in[4];
    const float* bn_g   = (const float*)d_in[5];
    const float* bn_bt  = (const float*)d_in[6];
    const float* bn_m   = (const float*)d_in[7];
    const float* bn_v   = (const float*)d_in[8];
    const float* gat_W  = (const float*)d_in[9];
    const float* att_s  = (const float*)d_in[10];
    const float* att_d  = (const float*)d_in[11];
    const float* gat_b  = (const float*)d_in[12];
    const float* c1W    = (const float*)d_in[13];
    const float* c1b    = (const float*)d_in[14];
    const float* c2W    = (const float*)d_in[15];
    const float* c2b    = (const float*)d_in[16];
    const float* c3W    = (const float*)d_in[17];
    const float* c3b    = (const float*)d_in[18];
    float* out = (float*)d_out;

    const int* src = ei;
    const int* dst = ei + N_EDGES;

    const int T = 256;
    const size_t NH = (size_t)N_NODES * HID;

    // Resolve ALL device-global scratch addresses properly (host code must not
    // reference __device__ symbols directly as pointers).
    float *p_h, *p_t, *p_agg, *p_hh, *p_emax, *p_denom, *p_gsum, *p_cnt;
    cudaGetSymbolAddress((void**)&p_h, g_h);
    cudaGetSymbolAddress((void**)&p_t, g_t);
    cudaGetSymbolAddress((void**)&p_agg, g_agg);
    cudaGetSymbolAddress((void**)&p_hh, g_hh);
    cudaGetSymbolAddress((void**)&p_emax, g_emax);
    cudaGetSymbolAddress((void**)&p_denom, g_denom);
    cudaGetSymbolAddress((void**)&p_gsum, g_gsum);
    cudaGetSymbolAddress((void**)&p_cnt, g_cnt);

    // degrees -> dinv
    deg_init_kernel<<<cdiv(N_NODES, T), T>>>();
    deg_accum_kernel<<<cdiv(N_EDGES, T), T>>>(dst);
    deg_finish_kernel<<<cdiv(N_NODES, T), T>>>();

    const int warp_items_blocks = cdiv((long long)N_ITEMS * 32, T);
    const int warp_nodes_blocks = cdiv((long long)N_NODES * 32, T);

    // 3 GCN layers
    for (int layer = 0; layer < 3; layer++) {
        const float* A = (layer == 0) ? x : p_h;
        gemm_k128<128><<<dim3(cdiv(N_NODES, 64), 1), T>>>(
            A, gcn_W + (size_t)layer * 128 * 128, p_t);
        zero_kernel<<<2048, T>>>(p_agg, NH);
        gcn_scatter_kernel<<<warp_items_blocks, T>>>(src, dst);
        bn_relu_kernel<<<cdiv((long long)NH, T), T>>>(gcn_b + layer * 128, bn_g + layer * 128,
                                                      bn_bt + layer * 128, bn_m + layer * 128,
                                                      bn_v + layer * 128, layer > 0);
    }

    // GAT
    gemm_k128<512><<<dim3(cdiv(N_NODES, 64), 4), T>>>(p_h, gat_W, p_hh);
    att_dots_kernel<<<warp_nodes_blocks, T>>>(att_s, att_d);
    zero_kernel<<<64, T>>>(p_emax, (size_t)N_NODES * HEADS);
    zero_kernel<<<64, T>>>(p_denom, (size_t)N_NODES * HEADS);
    att_emax_kernel<<<cdiv((long long)N_ITEMS * HEADS, T), T>>>(src, dst);
    att_emax_decode_kernel<<<cdiv((long long)N_NODES * HEADS, T), T>>>();
    att_denom_kernel<<<cdiv((long long)N_ITEMS * HEADS, T), T>>>(src, dst);
    zero_kernel<<<2048, T>>>(p_agg, NH);
    att_agg_kernel<<<warp_items_blocks, T>>>(src, dst);
    add_gat_kernel<<<cdiv((long long)NH, T), T>>>(gat_b);

    // pool + classifier
    zero_kernel<<<64, T>>>(p_gsum, (size_t)N_GRAPHS * HID);
    zero_kernel<<<8, T>>>(p_cnt, N_GRAPHS);
    pool_kernel<<<warp_nodes_blocks, T>>>(batch);
    mlp_kernel<<<N_GRAPHS, 64>>>(c1W, c1b, c2W, c2b, c3W, c3b, out);
}

// round 3
// speedup vs baseline: 1.5653x; 1.5653x over previous
#include <cuda_runtime.h>
#include <cuda_bf16.h>
#include <cstdint>

#define N_NODES 100000
#define N_EDGES 400000
#define HID 128
#define HEADS 4
#define N_GRAPHS 2000
#define NEG_SLOPE 0.2f
#define BN_EPS 1e-5f
#define N_ITEMS (N_EDGES + N_NODES)   // edges + self loops

#define SCAN_B 512
#define SCAN_NB ((N_NODES + SCAN_B - 1) / SCAN_B)

// ---------------- scratch (static device globals; no runtime alloc) ----------
__device__ int   g_degi[N_NODES];                  // degree incl self loop
__device__ float g_dinv[N_NODES];                  // rsqrt(deg)
__device__ int   g_off[N_NODES + 1];               // CSR offsets (by dst)
__device__ int   g_bsum[SCAN_NB];                  // scan partials
__device__ int   g_epos[N_NODES];                  // fill cursors
__device__ int   g_esrc[N_ITEMS];                  // CSR src-node ids
__device__ float g_h[(size_t)N_NODES * HID];       // node features
__device__ float g_t[(size_t)N_NODES * HID];       // t = h @ W
__device__ float g_hh[(size_t)N_NODES * HEADS * HID]; // GAT feats
__device__ float g_as[(size_t)N_NODES * HEADS];
__device__ float g_ad[(size_t)N_NODES * HEADS];

// ---------------- degree + CSR build -----------------------------------------
__global__ void deg_init_kernel() {
    int i = blockIdx.x * blockDim.x + threadIdx.x;
    if (i < N_NODES) g_degi[i] = 1;   // self loop
}
__global__ void deg_accum_kernel(const int* __restrict__ dst) {
    int e = blockIdx.x * blockDim.x + threadIdx.x;
    if (e < N_EDGES) atomicAdd(&g_degi[dst[e]], 1);
}
__global__ void deg_finish_kernel() {
    int i = blockIdx.x * blockDim.x + threadIdx.x;
    if (i < N_NODES) g_dinv[i] = rsqrtf((float)g_degi[i]);
}

// block-level inclusive scan of degrees -> g_off[i+1] (local), block totals
__global__ void scan_block_kernel() {
    __shared__ int sh[SCAN_B];
    int tid = threadIdx.x;
    int i = blockIdx.x * SCAN_B + tid;
    int v = (i < N_NODES) ? g_degi[i] : 0;
    sh[tid] = v;
    __syncthreads();
#pragma unroll
    for (int off = 1; off < SCAN_B; off <<= 1) {
        int t = (tid >= off) ? sh[tid - off] : 0;
        __syncthreads();
        sh[tid] += t;
        __syncthreads();
    }
    if (i < N_NODES) g_off[i + 1] = sh[tid];
    if (tid == SCAN_B - 1) g_bsum[blockIdx.x] = sh[tid];
}
__global__ void scan_bsums_kernel() {
    // single thread exclusive scan over SCAN_NB partials (tiny)
    if (threadIdx.x == 0 && blockIdx.x == 0) {
        int run = 0;
        for (int b = 0; b < SCAN_NB; b++) { int t = g_bsum[b]; g_bsum[b] = run; run += t; }
    }
}
__global__ void scan_add_kernel() {
    int tid = threadIdx.x;
    int i = blockIdx.x * SCAN_B + tid;
    if (i < N_NODES) g_off[i + 1] += g_bsum[blockIdx.x];
    if (i == 0) g_off[0] = 0;
}
__global__ void fill_self_kernel() {
    int d = blockIdx.x * blockDim.x + threadIdx.x;
    if (d < N_NODES) {
        int o = g_off[d];
        g_esrc[o] = d;          // self loop first
        g_epos[d] = o + 1;
    }
}
__global__ void fill_edges_kernel(const int* __restrict__ src, const int* __restrict__ dst) {
    int e = blockIdx.x * blockDim.x + threadIdx.x;
    if (e < N_EDGES) {
        int pos = atomicAdd(&g_epos[dst[e]], 1);
        g_esrc[pos] = src[e];
    }
}

// ---------------- SGEMM:  Out[N,C] = A[N,128] @ W[128,C] ---------------------
// 64-row x 128-col tile per CTA, 256 threads, 8x4 register microtile.
// FUSE_ATT: also emit a_s/a_d = <row, att_src/dst[head]> (head = blockIdx.y).
template <int C, bool FUSE_ATT>
__global__ void gemm_k128(const float* __restrict__ A, const float* __restrict__ W,
                          float* __restrict__ Out,
                          const float* __restrict__ att_src,
                          const float* __restrict__ att_dst,
                          float* __restrict__ as_out, float* __restrict__ ad_out) {
    __shared__ float As[64][32];
    __shared__ float Bs[32][128];
    const int tid = threadIdx.x;
    const int row0 = blockIdx.x * 64;
    const int cb = blockIdx.y * 128;
    const int ty = tid >> 5;            // warp id 0..7 -> row group
    const int lane = tid & 31;
    const int c0 = lane * 4;            // col within 128-tile
    float acc[8][4];
#pragma unroll
    for (int i = 0; i < 8; i++)
#pragma unroll
        for (int j = 0; j < 4; j++) acc[i][j] = 0.f;

    for (int kt = 0; kt < 128; kt += 32) {
#pragma unroll
        for (int i = 0; i < 2; i++) {
            int s = tid + i * 256;
            int r = s >> 3, k4 = (s & 7) * 4;
            int row = row0 + r;
            float4 v = make_float4(0.f, 0.f, 0.f, 0.f);
            if (row < N_NODES) v = *(const float4*)&A[(size_t)row * 128 + kt + k4];
            *(float4*)&As[r][k4] = v;
        }
#pragma unroll
        for (int i = 0; i < 4; i++) {
            int s = tid + i * 256;
            int k = s >> 5, c4 = (s & 31) * 4;
            *(float4*)&Bs[k][c4] = *(const float4*)&W[(size_t)(kt + k) * C + cb + c4];
        }
        __syncthreads();
#pragma unroll
        for (int k = 0; k < 32; k++) {
            float4 b = *(float4*)&Bs[k][c0];
#pragma unroll
            for (int i = 0; i < 8; i++) {
                float a = As[ty * 8 + i][k];
                acc[i][0] += a * b.x; acc[i][1] += a * b.y;
                acc[i][2] += a * b.z; acc[i][3] += a * b.w;
            }
        }
        __syncthreads();
    }
#pragma unroll
    for (int i = 0; i < 8; i++) {
        int row = row0 + ty * 8 + i;
        if (row < N_NODES) {
            float4 v = make_float4(acc[i][0], acc[i][1], acc[i][2], acc[i][3]);
            *(float4*)&Out[(size_t)row * C + cb + c0] = v;
        }
    }
    if (FUSE_ATT) {
        const int head = blockIdx.y;
        float4 ws = *(const float4*)&att_src[head * 128 + c0];
        float4 wd = *(const float4*)&att_dst[head * 128 + c0];
#pragma unroll
        for (int i = 0; i < 8; i++) {
            float ss = acc[i][0] * ws.x + acc[i][1] * ws.y + acc[i][2] * ws.z + acc[i][3] * ws.w;
            float sd = acc[i][0] * wd.x + acc[i][1] * wd.y + acc[i][2] * wd.z + acc[i][3] * wd.w;
#pragma unroll
            for (int o = 16; o; o >>= 1) {
                ss += __shfl_xor_sync(0xffffffffu, ss, o);
                sd += __shfl_xor_sync(0xffffffffu, sd, o);
            }
            if (lane == 0) {
                int row = row0 + ty * 8 + i;
                if (row < N_NODES) {
                    as_out[row * HEADS + head] = ss;
                    ad_out[row * HEADS + head] = sd;
                }
            }
        }
    }
}

// ---------------- GCN gather (CSR) + bias + BN + ReLU + residual -------------
// one warp per dst node
__global__ void gcn_gather_kernel(const float* __restrict__ t,
                                  const float* __restrict__ b, const float* __restrict__ gamma,
                                  const float* __restrict__ beta, const float* __restrict__ mean,
                                  const float* __restrict__ var, int residual) {
    int warp = (blockIdx.x * blockDim.x + threadIdx.x) >> 5;
    int lane = threadIdx.x & 31;
    if (warp >= N_NODES) return;
    const int d = warp;
    const float dd = g_dinv[d];
    const int beg = g_off[d], end = g_off[d + 1];
    const int c = lane * 4;
    float4 acc = make_float4(0.f, 0.f, 0.f, 0.f);
    for (int i = beg; i < end; i++) {
        int s = g_esrc[i];
        float w = dd * g_dinv[s];
        float4 v = *(const float4*)&t[(size_t)s * HID + c];
        acc.x += v.x * w; acc.y += v.y * w; acc.z += v.z * w; acc.w += v.w * w;
    }
    float4 bb = *(const float4*)&b[c];
    float4 mm = *(const float4*)&mean[c];
    float4 vv = *(const float4*)&var[c];
    float4 gg = *(const float4*)&gamma[c];
    float4 be = *(const float4*)&beta[c];
    float4 r;
    r.x = fmaxf((acc.x + bb.x - mm.x) * rsqrtf(vv.x + BN_EPS) * gg.x + be.x, 0.f);
    r.y = fmaxf((acc.y + bb.y - mm.y) * rsqrtf(vv.y + BN_EPS) * gg.y + be.y, 0.f);
    r.z = fmaxf((acc.z + bb.z - mm.z) * rsqrtf(vv.z + BN_EPS) * gg.z + be.z, 0.f);
    r.w = fmaxf((acc.w + bb.w - mm.w) * rsqrtf(vv.w + BN_EPS) * gg.w + be.w, 0.f);
    float* hp = &g_h[(size_t)d * HID + c];
    if (residual) {
        float4 hv = *(const float4*)hp;
        r.x += hv.x; r.y += hv.y; r.z += hv.z; r.w += hv.w;
    }
    *(float4*)hp = r;
}

__device__ __forceinline__ float leaky(float x) { return x > 0.f ? x : NEG_SLOPE * x; }

// ---------------- GAT: softmax (no max; cancels) + weighted gather + bias ----
// one warp per dst node; head-mean (0.25) folded into the reciprocal.
__global__ void gat_agg_kernel(const float* __restrict__ hh, const float* __restrict__ gat_b) {
    int warp = (blockIdx.x * blockDim.x + threadIdx.x) >> 5;
    int lane = threadIdx.x & 31;
    if (warp >= N_NODES) return;
    const int d = warp;
    const int beg = g_off[d], end = g_off[d + 1];
    const float4 ad4 = *(const float4*)&g_ad[(size_t)d * HEADS];

    // denominators (lanes stride edges)
    float4 ds = make_float4(0.f, 0.f, 0.f, 0.f);
    for (int i = beg + lane; i < end; i += 32) {
        int s = g_esrc[i];
        float4 as4 = *(const float4*)&g_as[(size_t)s * HEADS];
        ds.x += expf(leaky(as4.x + ad4.x));
        ds.y += expf(leaky(as4.y + ad4.y));
        ds.z += expf(leaky(as4.z + ad4.z));
        ds.w += expf(leaky(as4.w + ad4.w));
    }
#pragma unroll
    for (int o = 16; o; o >>= 1) {
        ds.x += __shfl_xor_sync(0xffffffffu, ds.x, o);
        ds.y += __shfl_xor_sync(0xffffffffu, ds.y, o);
        ds.z += __shfl_xor_sync(0xffffffffu, ds.z, o);
        ds.w += __shfl_xor_sync(0xffffffffu, ds.w, o);
    }
    float4 rcp;
    rcp.x = 0.25f / (ds.x + 1e-16f);
    rcp.y = 0.25f / (ds.y + 1e-16f);
    rcp.z = 0.25f / (ds.z + 1e-16f);
    rcp.w = 0.25f / (ds.w + 1e-16f);

    const int c = lane * 4;
    float4 acc = make_float4(0.f, 0.f, 0.f, 0.f);
    for (int i = beg; i < end; i++) {
        int s = g_esrc[i];
        float4 as4 = *(const float4*)&g_as[(size_t)s * HEADS];
        float a0 = expf(leaky(as4.x + ad4.x)) * rcp.x;
        float a1 = expf(leaky(as4.y + ad4.y)) * rcp.y;
        float a2 = expf(leaky(as4.z + ad4.z)) * rcp.z;
        float a3 = expf(leaky(as4.w + ad4.w)) * rcp.w;
        const float* p = hh + (size_t)s * (HEADS * HID) + c;
        float4 v0 = *(const float4*)p;
        float4 v1 = *(const float4*)(p + HID);
        float4 v2 = *(const float4*)(p + 2 * HID);
        float4 v3 = *(const float4*)(p + 3 * HID);
        acc.x += a0 * v0.x + a1 * v1.x + a2 * v2.x + a3 * v3.x;
        acc.y += a0 * v0.y + a1 * v1.y + a2 * v2.y + a3 * v3.y;
        acc.z += a0 * v0.z + a1 * v1.z + a2 * v2.z + a3 * v3.z;
        acc.w += a0 * v0.w + a1 * v1.w + a2 * v2.w + a3 * v3.w;
    }
    float4 bv = *(const float4*)&gat_b[c];
    float* hp = &g_h[(size_t)d * HID + c];
    float4 hv = *(const float4*)hp;
    hv.x += acc.x + bv.x; hv.y += acc.y + bv.y;
    hv.z += acc.z + bv.z; hv.w += acc.w + bv.w;
    *(float4*)hp = hv;
}

// ---------------- pool (sorted batch -> contiguous ranges) + MLP -------------
__global__ void pool_mlp_kernel(const int* __restrict__ batch,
                                const float* __restrict__ c1W, const float* __restrict__ c1b,
                                const float* __restrict__ c2W, const float* __restrict__ c2b,
                                const float* __restrict__ c3W, const float* __restrict__ c3b,
                                float* __restrict__ out) {
    const int g = blockIdx.x;
    const int tid = threadIdx.x;   // 128 threads
    __shared__ int sbeg, send;
    __shared__ float gv[128];
    __shared__ float z1[64];
    __shared__ float z2[32];
    if (tid == 0) {
        int lo = 0, hi = N_NODES;
        while (lo < hi) { int mid = (lo + hi) >> 1; if (batch[mid] < g) lo = mid + 1; else hi = mid; }
        sbeg = lo;
        lo = sbeg; hi = N_NODES;
        while (lo < hi) { int mid = (lo + hi) >> 1; if (batch[mid] < g + 1) lo = mid + 1; else hi = mid; }
        send = lo;
    }
    __syncthreads();
    const int beg = sbeg, end = send;
    float s = 0.f;
    for (int r = beg; r < end; r++) s += g_h[(size_t)r * HID + tid];
    float cnt = fmaxf((float)(end - beg), 1.0f);
    gv[tid] = s / cnt;
    __syncthreads();
    if (tid < 64) {
        float z = c1b[tid];
#pragma unroll 8
        for (int k = 0; k < 128; k++) z += gv[k] * c1W[k * 64 + tid];
        z1[tid] = fmaxf(z, 0.f);
    }
    __syncthreads();
    if (tid < 32) {
        float z = c2b[tid];
#pragma unroll 8
        for (int k = 0; k < 64; k++) z += z1[k] * c2W[k * 32 + tid];
        z2[tid] = fmaxf(z, 0.f);
        __syncwarp();
        float p = z2[tid] * c3W[tid];
#pragma unroll
        for (int o = 16; o; o >>= 1) p += __shfl_xor_sync(0xffffffffu, p, o);
        if (tid == 0) out[g] = p + c3b[0];
    }
}

// -----------------------------------------------------------------------------
static inline int cdiv(long long a, int b) { return (int)((a + b - 1) / b); }

extern "C" void kernel_launch(void* const* d_in, const int* in_sizes, int n_in,
                              void* d_out, int out_size) {
    const float* x      = (const float*)d_in[0];
    const int*   ei     = (const int*)d_in[1];
    const int*   batch  = (const int*)d_in[2];
    const float* gcn_W  = (const float*)d_in[3];
    const float* gcn_b  = (const float*)d_in[4];
    const float* bn_g   = (const float*)d_in[5];
    const float* bn_bt  = (const float*)d_in[6];
    const float* bn_m   = (const float*)d_in[7];
    const float* bn_v   = (const float*)d_in[8];
    const float* gat_W  = (const float*)d_in[9];
    const float* att_s  = (const float*)d_in[10];
    const float* att_d  = (const float*)d_in[11];
    const float* gat_b  = (const float*)d_in[12];
    const float* c1W    = (const float*)d_in[13];
    const float* c1b    = (const float*)d_in[14];
    const float* c2W    = (const float*)d_in[15];
    const float* c2b    = (const float*)d_in[16];
    const float* c3W    = (const float*)d_in[17];
    const float* c3b    = (const float*)d_in[18];
    float* out = (float*)d_out;

    const int* src = ei;
    const int* dst = ei + N_EDGES;
    const int T = 256;

    float *p_h, *p_t, *p_hh, *p_as, *p_ad;
    cudaGetSymbolAddress((void**)&p_h, g_h);
    cudaGetSymbolAddress((void**)&p_t, g_t);
    cudaGetSymbolAddress((void**)&p_hh, g_hh);
    cudaGetSymbolAddress((void**)&p_as, g_as);
    cudaGetSymbolAddress((void**)&p_ad, g_ad);

    // ---- CSR build (by dst) + dinv ----
    deg_init_kernel<<<cdiv(N_NODES, T), T>>>();
    deg_accum_kernel<<<cdiv(N_EDGES, T), T>>>(dst);
    deg_finish_kernel<<<cdiv(N_NODES, T), T>>>();
    scan_block_kernel<<<SCAN_NB, SCAN_B>>>();
    scan_bsums_kernel<<<1, 32>>>();
    scan_add_kernel<<<SCAN_NB, SCAN_B>>>();
    fill_self_kernel<<<cdiv(N_NODES, T), T>>>();
    fill_edges_kernel<<<cdiv(N_EDGES, T), T>>>(src, dst);

    const int warp_nodes_blocks = cdiv((long long)N_NODES * 32, T);

    // ---- 3 GCN layers ----
    for (int layer = 0; layer < 3; layer++) {
        const float* A = (layer == 0) ? x : p_h;
        gemm_k128<128, false><<<dim3(cdiv(N_NODES, 64), 1), T>>>(
            A, gcn_W + (size_t)layer * 128 * 128, p_t, nullptr, nullptr, nullptr, nullptr);
        gcn_gather_kernel<<<warp_nodes_blocks, T>>>(
            p_t, gcn_b + layer * 128, bn_g + layer * 128, bn_bt + layer * 128,
            bn_m + layer * 128, bn_v + layer * 128, layer > 0);
    }

    // ---- GAT ----
    gemm_k128<512, true><<<dim3(cdiv(N_NODES, 64), 4), T>>>(
        p_h, gat_W, p_hh, att_s, att_d, p_as, p_ad);
    gat_agg_kernel<<<warp_nodes_blocks, T>>>(p_hh, gat_b);

    // ---- pool + classifier ----
    pool_mlp_kernel<<<N_GRAPHS, 128>>>(batch, c1W, c1b, c2W, c2b, c3W, c3b, out);
}